// round 12
// baseline (speedup 1.0000x reference)
#include <cuda_runtime.h>
#include <cstdint>

// Problem constants
#define BB    8
#define FF    6
#define FM1   5          // frames used (1..5)
#define NBUF  5
#define NSLOT 7
#define HH    192
#define WW    192
#define CC    3
#define HW    (HH*WW)    // 36864

#define TPB   128
#define CHUNK_PX 256                        // pixels per chunk
#define CHUNKS_PER_IMG (HW/CHUNK_PX)        // 144
#define NIMG  (BB*FM1)                      // 40
#define TOTAL_CHUNKS (NIMG*CHUNKS_PER_IMG)  // 5760
#define GRID_MAIN 288                       // single wave (>=2 blocks/SM)
#define ITERS (TOTAL_CHUNKS/GRID_MAIN)      // 20
#define STAGES 2

// Stream layout per stage (each stream = CHUNK_PX floats = 1KB):
// 0..6 masks | 7..11 seg | 12..18 vis | 19..21 tgt | 22..36 rec
#define NSTREAM 37
#define STAGE_FLOATS (NSTREAM*CHUNK_PX)     // 9472
#define SMEM_BYTES (STAGES*STAGE_FLOATS*4)  // 75776

#define EPSF   1e-7f
#define OMEPSF (1.0f - 1e-7f)

__device__ float g_partials[GRID_MAIN];
__device__ unsigned int g_ticket = 0;

extern __shared__ float smbuf[];

__device__ __forceinline__ void cpa16(uint32_t saddr, const float* __restrict__ g) {
    asm volatile("cp.async.cg.shared.global [%0], [%1], 16;\n" :: "r"(saddr), "l"(g));
}

__device__ __forceinline__ void prefetch_chunk(
    uint32_t sbase, int base, int pix0,
    const float* __restrict__ seg,  const float* __restrict__ masks,
    const float* __restrict__ rec,  const float* __restrict__ tgt,
    const float* __restrict__ vis,  int half, int goff)
{
    #pragma unroll
    for (int s = 0; s < NSLOT; s += 2) {
        int ss = s + half;
        if (ss < NSLOT)
            cpa16(sbase + (uint32_t)(ss*CHUNK_PX + goff)*4u,
                  masks + (size_t)(base*NSLOT + ss)*HW + pix0 + goff);
    }
    #pragma unroll
    for (int n = 0; n < NBUF; n += 2) {
        int nn = n + half;
        if (nn < NBUF)
            cpa16(sbase + (uint32_t)((7+nn)*CHUNK_PX + goff)*4u,
                  seg + (size_t)(base*NBUF + nn)*HW + pix0 + goff);
    }
    #pragma unroll
    for (int s = 0; s < NSLOT; s += 2) {
        int ss = s + half;
        if (ss < NSLOT)
            cpa16(sbase + (uint32_t)((12+ss)*CHUNK_PX + goff)*4u,
                  vis + (size_t)(base*NSLOT + ss)*HW + pix0 + goff);
    }
    #pragma unroll
    for (int c = 0; c < CC; c += 2) {
        int cc2 = c + half;
        if (cc2 < CC)
            cpa16(sbase + (uint32_t)((19+cc2)*CHUNK_PX + goff)*4u,
                  tgt + (size_t)(base*CC + cc2)*HW + pix0 + goff);
    }
    #pragma unroll
    for (int k = 0; k < NBUF*CC; k += 2) {
        int kk = k + half;
        if (kk < NBUF*CC)
            cpa16(sbase + (uint32_t)((22+kk)*CHUNK_PX + goff)*4u,
                  rec + (size_t)(base*NBUF*CC + kk)*HW + pix0 + goff);
    }
}

// img index (0..39) -> base offset index b*FF+f
__device__ __forceinline__ int img_base(int img) {
    return (img / FM1) * FF + (img % FM1) + 1;
}

__global__ __launch_bounds__(TPB)
void em_main(const float* __restrict__ seg,
             const float* __restrict__ masks,
             const float* __restrict__ rec,
             const float* __restrict__ tgt,
             const float* __restrict__ vis,
             const float* __restrict__ attn,
             float* __restrict__ out)
{
    __shared__ float sAttnH[NSLOT][NBUF];   // attn * (1/HW)
    __shared__ float sAttnK[NSLOT][NBUF];   // attn * (0.1/C)
    __shared__ float sA[NBUF];              // (1/HW) * sum_s attn[s][n]
    __shared__ float wsum[TPB / 32];
    __shared__ bool  isLast;

    const int tid = (int)threadIdx.x;
    const int k   = (int)blockIdx.x;        // 0..287
    const int k1  = (k >= CHUNKS_PER_IMG) ? 1 : 0;
    const int pix0 = (k - k1*CHUNKS_PER_IMG) * CHUNK_PX;   // loop-invariant

    const uint32_t smem0 = (uint32_t)__cvta_generic_to_shared(smbuf);
    const int half = tid >> 6;              // 0/1
    const int goff = (tid & 63) * 4;        // float offset of 16B unit

    const float invHW = 1.0f / (float)HW;
    const float Kc    = 0.1f / (float)CC;

    // ---------------- pipeline prologue: prefetch chunks 0 and 1 ----------------
    prefetch_chunk(smem0, img_base(2*0 + k1), pix0, seg, masks, rec, tgt, vis, half, goff);
    asm volatile("cp.async.commit_group;\n" ::: "memory");
    prefetch_chunk(smem0 + STAGE_FLOATS*4u, img_base(2*1 + k1), pix0, seg, masks, rec, tgt, vis, half, goff);
    asm volatile("cp.async.commit_group;\n" ::: "memory");

    float acc0 = 0.0f, acc1 = 0.0f;

    #pragma unroll 1
    for (int it = 0; it < ITERS; it++) {
        // ---- prefetch chunk it+2 into buf[it%2] is WRONG buffer; it+2 uses buf[(it+2)%2] = buf[it%2].
        // buf[it%2] is being computed THIS iteration -> must prefetch AFTER compute.
        // Instead: issue prefetch for it+2 at END of iteration (after the closing barrier).
        // To keep group-counting simple, the commit for it+2 happens there too.

        // ---- attn coefficients for current image (img = 2*it + k1) ----
        const int base = img_base(2*it + k1);
        if (tid < NSLOT * NBUF) {
            int s = tid / NBUF, n = tid % NBUF;
            float a = attn[(base*NSLOT + s)*NBUF + n];
            sAttnH[s][n] = a * invHW;
            sAttnK[s][n] = a * Kc;
        }
        if (tid >= 64 && tid < 64 + NBUF) {
            int n = tid - 64;
            float sum = 0.0f;
            #pragma unroll
            for (int s = 0; s < NSLOT; s++)
                sum += attn[(base*NSLOT + s)*NBUF + n];
            sA[n] = sum * invHW;
        }

        // ---- wait for current chunk's data (at most 1 newer group outstanding) ----
        asm volatile("cp.async.wait_group 1;\n" ::: "memory");
        __syncthreads();     // chunk data + sAttn visible to all

        const float2* sm2 = reinterpret_cast<const float2*>(smbuf + (it & 1) * STAGE_FLOATS);
        #define SM2(s) sm2[(s)*(CHUNK_PX/2) + tid]

        // ===== BCE =====
        float T[NBUF][2];
        #pragma unroll
        for (int n = 0; n < NBUF; n++) { T[n][0] = 0.0f; T[n][1] = 0.0f; }

        #pragma unroll
        for (int s = 0; s < NSLOT; s++) {
            float2 m = SM2(s);
            float tb0 = (m.x > 0.5f) ? 1.0f : 0.0f;
            float tb1 = (m.y > 0.5f) ? 1.0f : 0.0f;
            #pragma unroll
            for (int n = 0; n < NBUF; n++) {
                float aH = sAttnH[s][n];
                T[n][0] = fmaf(tb0, aH, T[n][0]);
                T[n][1] = fmaf(tb1, aH, T[n][1]);
            }
        }

        #pragma unroll
        for (int n = 0; n < NBUF; n++) {
            float2 p = SM2(7+n);
            const float An = sA[n];
            {
                float pc  = fminf(fmaxf(p.x, EPSF), OMEPSF);
                float lp  = __logf(pc);
                float l1m = __logf(1.0f - pc);   // == log1p(-p) in fp32 (Sterbenz)
                acc0 = fmaf(-T[n][0], lp, acc0);
                acc0 = fmaf(T[n][0] - An, l1m, acc0);
            }
            {
                float pc  = fminf(fmaxf(p.y, EPSF), OMEPSF);
                float lp  = __logf(pc);
                float l1m = __logf(1.0f - pc);
                acc1 = fmaf(-T[n][1], lp, acc1);
                acc1 = fmaf(T[n][1] - An, l1m, acc1);
            }
        }

        // ===== masked MSE =====
        float V[NBUF][2];
        #pragma unroll
        for (int n = 0; n < NBUF; n++) { V[n][0] = 0.0f; V[n][1] = 0.0f; }

        #pragma unroll
        for (int s = 0; s < NSLOT; s++) {
            float2 v = SM2(12+s);
            float vb0 = (v.x > 0.5f) ? 1.0f : 0.0f;
            float vb1 = (v.y > 0.5f) ? 1.0f : 0.0f;
            #pragma unroll
            for (int n = 0; n < NBUF; n++) {
                float aK = sAttnK[s][n];
                V[n][0] = fmaf(vb0, aK, V[n][0]);
                V[n][1] = fmaf(vb1, aK, V[n][1]);
            }
        }

        float tg[CC][2];
        #pragma unroll
        for (int c = 0; c < CC; c++) {
            float2 t = SM2(19+c);
            tg[c][0] = t.x; tg[c][1] = t.y;
        }

        #pragma unroll
        for (int n = 0; n < NBUF; n++) {
            float d20 = 0.0f, d21 = 0.0f;
            #pragma unroll
            for (int c = 0; c < CC; c++) {
                float2 r = SM2(22 + n*CC + c);
                float dd0 = r.x - tg[c][0];
                float dd1 = r.y - tg[c][1];
                d20 = fmaf(dd0, dd0, d20);
                d21 = fmaf(dd1, dd1, d21);
            }
            acc0 = fmaf(V[n][0], d20, acc0);
            acc1 = fmaf(V[n][1], d21, acc1);
        }
        #undef SM2

        __syncthreads();     // all warps done reading buf[it&1] and sAttn

        // ---- prefetch chunk it+2 into buf[it&1] (just freed) ----
        if (it + 2 < ITERS) {
            prefetch_chunk(smem0 + (uint32_t)(it & 1) * STAGE_FLOATS * 4u,
                           img_base(2*(it+2) + k1), pix0,
                           seg, masks, rec, tgt, vis, half, goff);
        }
        asm volatile("cp.async.commit_group;\n" ::: "memory");  // empty group OK at tail
    }

    // ================= block reduction =================
    float tot = acc0 + acc1;
    #pragma unroll
    for (int o = 16; o > 0; o >>= 1)
        tot += __shfl_down_sync(0xffffffffu, tot, o);

    if ((tid & 31) == 0) wsum[tid >> 5] = tot;
    __syncthreads();

    if (tid == 0) {
        float s = 0.0f;
        #pragma unroll
        for (int i = 0; i < TPB / 32; i++) s += wsum[i];
        g_partials[blockIdx.x] = s;
        __threadfence();
        unsigned prev = atomicAdd(&g_ticket, 1u);
        isLast = (prev == GRID_MAIN - 1);
    }
    __syncthreads();

    // ================= last block: final deterministic reduction =================
    if (isLast) {
        float v = 0.0f;
        #pragma unroll 1
        for (int i = tid; i < GRID_MAIN; i += TPB)
            v += g_partials[i];              // fixed strided order -> deterministic
        #pragma unroll
        for (int o = 16; o > 0; o >>= 1)
            v += __shfl_down_sync(0xffffffffu, v, o);
        if ((tid & 31) == 0) wsum[tid >> 5] = v;
        __syncthreads();
        if (tid == 0) {
            float s = 0.0f;
            #pragma unroll
            for (int i = 0; i < TPB / 32; i++) s += wsum[i];
            // total / (B*(F-1)*NB*NS) * LOSS_WEIGHT = total * 20/1400
            out[0] = s * (20.0f / 1400.0f);
            atomicExch(&g_ticket, 0u);       // reset for next graph replay
        }
    }
}

extern "C" void kernel_launch(void* const* d_in, const int* in_sizes, int n_in,
                              void* d_out, int out_size)
{
    const float* seg   = (const float*)d_in[0];  // segmentations   [B,F,NB,H,W]
    const float* masks = (const float*)d_in[1];  // masks           [B,F,NS,H,W]
    const float* rec   = (const float*)d_in[2];  // reconstructions [B,F,NB,C,H,W]
    const float* tgt   = (const float*)d_in[3];  // rec_tgt         [B,F,C,H,W]
    const float* vis   = (const float*)d_in[4];  // masks_vis       [B,F,NS,H,W]
    const float* attn  = (const float*)d_in[5];  // attn_index      [B,F,NS,NB]
    (void)in_sizes; (void)n_in; (void)out_size;

    cudaFuncSetAttribute(em_main, cudaFuncAttributeMaxDynamicSharedMemorySize, SMEM_BYTES);
    em_main<<<GRID_MAIN, TPB, SMEM_BYTES>>>(seg, masks, rec, tgt, vis, attn, (float*)d_out);
}

// round 15
// speedup vs baseline: 1.1363x; 1.1363x over previous
#include <cuda_runtime.h>
#include <cstdint>

// Problem constants
#define BB    8
#define FF    6
#define FM1   5          // frames used (1..5)
#define NBUF  5
#define NSLOT 7
#define HH    192
#define WW    192
#define CC    3
#define HW    (HH*WW)    // 36864

#define TPB   256
#define CHUNK_PX 256                        // pixels per block; 1 px per thread
#define CHUNKS_PER_IMG (HW/CHUNK_PX)        // 144
#define NIMG  (BB*FM1)                      // 40
#define GRID_MAIN (NIMG*CHUNKS_PER_IMG)     // 5760

// Stream layout in SMEM (each stream = CHUNK_PX floats = 1KB)
// 0..6   masks s            (group 0)
// 7..11  seg n              (group 0)
// 12..18 vis s              (group 1)
// 19..21 tgt c              (group 1)
// 22..36 rec n*3+c          (group 2)
#define NSTREAM 37

#define EPSF   1e-7f
#define OMEPSF (1.0f - 1e-7f)

__device__ float g_partials[GRID_MAIN];
__device__ unsigned int g_ticket = 0;

__device__ __forceinline__ void cpa16(uint32_t saddr, const float* __restrict__ g) {
    asm volatile("cp.async.cg.shared.global [%0], [%1], 16;\n" :: "r"(saddr), "l"(g));
}

__global__ __launch_bounds__(TPB, 6)
void em_main(const float* __restrict__ seg,
             const float* __restrict__ masks,
             const float* __restrict__ rec,
             const float* __restrict__ tgt,
             const float* __restrict__ vis,
             const float* __restrict__ attn,
             float* __restrict__ out)
{
    __shared__ float sm_data[NSTREAM * CHUNK_PX];   // 37 KB
    __shared__ float sAttnH[NSLOT][NBUF];           // attn * (1/HW)
    __shared__ float sAttnK[NSLOT][NBUF];           // attn * (0.1/C)
    __shared__ float sA[NBUF];                      // (1/HW) * sum_s attn[s][n]
    __shared__ float wsum[TPB / 32];
    __shared__ bool  isLast;

    const int tid   = (int)threadIdx.x;
    const int cid   = (int)blockIdx.x;
    const int img   = cid / CHUNKS_PER_IMG;
    const int chunk = cid % CHUNKS_PER_IMG;
    const int b = img / FM1;
    const int f = img % FM1 + 1;           // skip frame 0
    const int base = b*FF + f;
    const int pix0 = chunk * CHUNK_PX;

    // ---------------- issue all async copies ----------------
    // 64 16B-units per stream; 256 threads -> 4 streams serviced per pass.
    const uint32_t smem0 = (uint32_t)__cvta_generic_to_shared(sm_data);
    const int q    = tid >> 6;             // 0..3: which stream of a quad
    const int goff = (tid & 63) * 4;       // float offset of this 16B unit

    // group 0: masks (7) + seg (5) = streams 0..11
    #pragma unroll
    for (int s0 = 0; s0 < 12; s0 += 4) {
        int st = s0 + q;                   // stream id 0..11
        const float* gp = (st < NSLOT)
            ? masks + (size_t)(base*NSLOT + st)*HW + pix0 + goff
            : seg   + (size_t)(base*NBUF + (st-7))*HW + pix0 + goff;
        cpa16(smem0 + (uint32_t)(st*CHUNK_PX + goff)*4u, gp);
    }
    asm volatile("cp.async.commit_group;\n" ::: "memory");

    // group 1: vis (7) + tgt (3) = streams 12..21
    #pragma unroll
    for (int s0 = 0; s0 < 12; s0 += 4) {
        int st = s0 + q;                   // 0..11, maps to stream 12+st
        if (st < 10) {
            const float* gp = (st < NSLOT)
                ? vis + (size_t)(base*NSLOT + st)*HW + pix0 + goff
                : tgt + (size_t)(base*CC + (st-7))*HW + pix0 + goff;
            cpa16(smem0 + (uint32_t)((12+st)*CHUNK_PX + goff)*4u, gp);
        }
    }
    asm volatile("cp.async.commit_group;\n" ::: "memory");

    // group 2: rec (15) = streams 22..36
    #pragma unroll
    for (int s0 = 0; s0 < 16; s0 += 4) {
        int st = s0 + q;                   // 0..15
        if (st < NBUF*CC)
            cpa16(smem0 + (uint32_t)((22+st)*CHUNK_PX + goff)*4u,
                  rec + (size_t)(base*NBUF*CC + st)*HW + pix0 + goff);
    }
    asm volatile("cp.async.commit_group;\n" ::: "memory");

    // ---------------- attn coefficients (overlaps copies) ----------------
    const float invHW = 1.0f / (float)HW;
    const float Kc    = 0.1f / (float)CC;
    if (tid < NSLOT * NBUF) {
        int s = tid / NBUF, n = tid % NBUF;
        float a = attn[(base*NSLOT + s)*NBUF + n];
        sAttnH[s][n] = a * invHW;
        sAttnK[s][n] = a * Kc;
    }
    if (tid >= 64 && tid < 64 + NBUF) {
        int n = tid - 64;
        float sum = 0.0f;
        #pragma unroll
        for (int s = 0; s < NSLOT; s++)
            sum += attn[(base*NSLOT + s)*NBUF + n];
        sA[n] = sum * invHW;
    }

    #define SM(s) sm_data[(s)*CHUNK_PX + tid]

    float acc = 0.0f;

    // ================= Phase A: BCE (needs group 0) =================
    asm volatile("cp.async.wait_group 2;\n" ::: "memory");
    __syncthreads();   // group-0 data + sAttn/sA visible to all

    float T[NBUF];
    #pragma unroll
    for (int n = 0; n < NBUF; n++) T[n] = 0.0f;

    #pragma unroll
    for (int s = 0; s < NSLOT; s++) {
        float tb = (SM(s) > 0.5f) ? 1.0f : 0.0f;
        #pragma unroll
        for (int n = 0; n < NBUF; n++)
            T[n] = fmaf(tb, sAttnH[s][n], T[n]);
    }

    #pragma unroll
    for (int n = 0; n < NBUF; n++) {
        float p   = SM(7+n);
        float An  = sA[n];
        float pc  = fminf(fmaxf(p, EPSF), OMEPSF);
        float lp  = __logf(pc);
        float l1m = __logf(1.0f - pc);     // == log1p(-p) in fp32 (Sterbenz)
        acc = fmaf(-T[n], lp, acc);
        acc = fmaf(T[n] - An, l1m, acc);
    }

    // ================= Phase B: V + tgt (needs group 1) =================
    asm volatile("cp.async.wait_group 1;\n" ::: "memory");
    __syncthreads();

    float V[NBUF];
    #pragma unroll
    for (int n = 0; n < NBUF; n++) V[n] = 0.0f;

    #pragma unroll
    for (int s = 0; s < NSLOT; s++) {
        float vb = (SM(12+s) > 0.5f) ? 1.0f : 0.0f;
        #pragma unroll
        for (int n = 0; n < NBUF; n++)
            V[n] = fmaf(vb, sAttnK[s][n], V[n]);
    }

    float tg[CC];
    #pragma unroll
    for (int c = 0; c < CC; c++) tg[c] = SM(19+c);

    // ================= Phase C: MSE (needs group 2) =================
    asm volatile("cp.async.wait_group 0;\n" ::: "memory");
    __syncthreads();

    #pragma unroll
    for (int n = 0; n < NBUF; n++) {
        float d2 = 0.0f;
        #pragma unroll
        for (int c = 0; c < CC; c++) {
            float dd = SM(22 + n*CC + c) - tg[c];
            d2 = fmaf(dd, dd, d2);
        }
        acc = fmaf(V[n], d2, acc);
    }
    #undef SM

    // ================= block reduction =================
    float tot = acc;
    #pragma unroll
    for (int o = 16; o > 0; o >>= 1)
        tot += __shfl_down_sync(0xffffffffu, tot, o);

    if ((tid & 31) == 0) wsum[tid >> 5] = tot;
    __syncthreads();

    if (tid == 0) {
        float s = 0.0f;
        #pragma unroll
        for (int i = 0; i < TPB / 32; i++) s += wsum[i];
        g_partials[blockIdx.x] = s;
        __threadfence();
        unsigned prev = atomicAdd(&g_ticket, 1u);
        isLast = (prev == GRID_MAIN - 1);
    }
    __syncthreads();

    // ================= last block: final deterministic reduction =================
    if (isLast) {
        // 5760 / 256 = 22.5 per thread; fixed strided order -> deterministic.
        float v0 = 0.0f, v1 = 0.0f;
        #pragma unroll 1
        for (int i = tid; i < GRID_MAIN; i += TPB * 2) {
            v0 += g_partials[i];
            float x = (i + TPB < GRID_MAIN) ? g_partials[i + TPB] : 0.0f;
            v1 += x;
        }
        float v = v0 + v1;
        #pragma unroll
        for (int o = 16; o > 0; o >>= 1)
            v += __shfl_down_sync(0xffffffffu, v, o);
        if ((tid & 31) == 0) wsum[tid >> 5] = v;
        __syncthreads();
        if (tid == 0) {
            float s = 0.0f;
            #pragma unroll
            for (int i = 0; i < TPB / 32; i++) s += wsum[i];
            // total / (B*(F-1)*NB*NS) * LOSS_WEIGHT = total * 20/1400
            out[0] = s * (20.0f / 1400.0f);
            atomicExch(&g_ticket, 0u);          // reset for next graph replay
        }
    }
}

extern "C" void kernel_launch(void* const* d_in, const int* in_sizes, int n_in,
                              void* d_out, int out_size)
{
    const float* seg   = (const float*)d_in[0];  // segmentations   [B,F,NB,H,W]
    const float* masks = (const float*)d_in[1];  // masks           [B,F,NS,H,W]
    const float* rec   = (const float*)d_in[2];  // reconstructions [B,F,NB,C,H,W]
    const float* tgt   = (const float*)d_in[3];  // rec_tgt         [B,F,C,H,W]
    const float* vis   = (const float*)d_in[4];  // masks_vis       [B,F,NS,H,W]
    const float* attn  = (const float*)d_in[5];  // attn_index      [B,F,NS,NB]
    (void)in_sizes; (void)n_in; (void)out_size;

    em_main<<<GRID_MAIN, TPB>>>(seg, masks, rec, tgt, vis, attn, (float*)d_out);
}